// round 2
// baseline (speedup 1.0000x reference)
#include <cuda_runtime.h>

#define TOKENS   16384
#define KDIM     8192
#define MTILE    64
#define NTHREADS 128
#define KSTAGE   64
#define NSTAGES  (KDIM / KSTAGE)   /* 128 */
#define XSTRIDE  68                /* floats; 68 % 32 == 4 -> conflict-free frags */
#define WSTRIDE  68
#define NOUT     24

__device__ __forceinline__ void mma_tf32(float c[4],
                                         unsigned a0, unsigned a1, unsigned a2, unsigned a3,
                                         unsigned b0, unsigned b1) {
    asm volatile(
        "mma.sync.aligned.m16n8k8.row.col.f32.tf32.tf32.f32 "
        "{%0,%1,%2,%3}, {%4,%5,%6,%7}, {%8,%9}, {%0,%1,%2,%3};\n"
        : "+f"(c[0]), "+f"(c[1]), "+f"(c[2]), "+f"(c[3])
        : "r"(a0), "r"(a1), "r"(a2), "r"(a3), "r"(b0), "r"(b1));
}

__device__ __forceinline__ void cp_async16(void* smem_dst, const void* gsrc) {
    unsigned dst = (unsigned)__cvta_generic_to_shared(smem_dst);
    asm volatile("cp.async.cg.shared.global [%0], [%1], 16;\n" :: "r"(dst), "l"(gsrc));
}

__global__ void __launch_bounds__(NTHREADS)
mhc_kernel(const float* __restrict__ x,
           const float* __restrict__ a_pre_p, const float* __restrict__ a_post_p,
           const float* __restrict__ a_res_p,
           const float* __restrict__ b_pre, const float* __restrict__ b_post,
           const float* __restrict__ b_res,
           const float* __restrict__ W_pre, const float* __restrict__ W_post,
           const float* __restrict__ W_res,
           float* __restrict__ out)
{
    __shared__ float xs[2][MTILE * XSTRIDE];   // 2*64*68*4 = 34816 B
    __shared__ float ws[2][NOUT * WSTRIDE];    // 2*24*68*4 = 13056 B

    const int tid  = threadIdx.x;
    const int lane = tid & 31;
    const int warp = tid >> 5;
    const int g    = lane >> 2;   // group id (row within m16 tile)
    const int tig  = lane & 3;    // thread-in-group (k / n-pair index)
    const int tokbase = blockIdx.x * MTILE;

    // ---- staging assignments ----
    const int stok = tid >> 4;          // 0..7 (token rows stok + 8i)
    const int c4   = (tid & 15) * 4;    // float offset within the 64-float stage

    // W rows for this thread: r0, r0+8, r0+16  (combined matrix: 0-3 pre, 4-7 post, 8-23 res)
    const float* wrowp[3];
    {
        int r0 = tid >> 4;
        wrowp[0] = (r0 < 4) ? (W_pre + (size_t)r0 * KDIM) : (W_post + (size_t)(r0 - 4) * KDIM);
        wrowp[1] = W_res + (size_t)(r0)     * KDIM;  // rows 8..15  -> res 0..7
        wrowp[2] = W_res + (size_t)(r0 + 8) * KDIM;  // rows 16..23 -> res 8..15
    }

    float acc[3][4];
    #pragma unroll
    for (int n = 0; n < 3; n++)
        #pragma unroll
        for (int j = 0; j < 4; j++) acc[n][j] = 0.f;

    // ---- prefetch stage 0 ----
    {
        #pragma unroll
        for (int i = 0; i < 8; i++) {
            int tok = stok + i * 8;
            cp_async16(&xs[0][tok * XSTRIDE + c4],
                       x + (size_t)(tokbase + tok) * KDIM + c4);
        }
        #pragma unroll
        for (int i = 0; i < 3; i++) {
            int row = (tid >> 4) + i * 8;
            cp_async16(&ws[0][row * WSTRIDE + c4], wrowp[i] + c4);
        }
        asm volatile("cp.async.commit_group;\n");
    }

    #pragma unroll 1
    for (int s = 0; s < NSTAGES; s++) {
        const int buf = s & 1;
        if (s + 1 < NSTAGES) {
            const int kb = (s + 1) * KSTAGE;
            const int nb = buf ^ 1;
            #pragma unroll
            for (int i = 0; i < 8; i++) {
                int tok = stok + i * 8;
                cp_async16(&xs[nb][tok * XSTRIDE + c4],
                           x + (size_t)(tokbase + tok) * KDIM + kb + c4);
            }
            #pragma unroll
            for (int i = 0; i < 3; i++) {
                int row = (tid >> 4) + i * 8;
                cp_async16(&ws[nb][row * WSTRIDE + c4], wrowp[i] + kb + c4);
            }
            asm volatile("cp.async.commit_group;\n");
            asm volatile("cp.async.wait_group 1;\n");
        } else {
            asm volatile("cp.async.wait_group 0;\n");
        }
        __syncthreads();

        const float* xr0 = &xs[buf][(warp * 16 + g) * XSTRIDE + tig];
        const float* xr1 = xr0 + 8 * XSTRIDE;
        const float* wr  = &ws[buf][g * WSTRIDE + tig];

        #pragma unroll
        for (int st = 0; st < KSTAGE / 8; st++) {
            unsigned a0 = __float_as_uint(xr0[st * 8]);
            unsigned a2 = __float_as_uint(xr0[st * 8 + 4]);
            unsigned a1 = __float_as_uint(xr1[st * 8]);
            unsigned a3 = __float_as_uint(xr1[st * 8 + 4]);
            #pragma unroll
            for (int nt = 0; nt < 3; nt++) {
                unsigned b0 = __float_as_uint(wr[nt * 8 * WSTRIDE + st * 8]);
                unsigned b1 = __float_as_uint(wr[nt * 8 * WSTRIDE + st * 8 + 4]);
                mma_tf32(acc[nt], a0, a1, a2, a3, b0, b1);
            }
        }
        __syncthreads();
    }

    // ---- epilogue: gather 24 outputs per token into smem, then per-token math ----
    float* accs = &xs[0][0];   // 64 * 25 floats, reuse x staging buffer
    {
        int t0 = warp * 16 + g;
        #pragma unroll
        for (int nt = 0; nt < 3; nt++) {
            int n0 = nt * 8 + tig * 2;
            accs[t0 * 25 + n0]           = acc[nt][0];
            accs[t0 * 25 + n0 + 1]       = acc[nt][1];
            accs[(t0 + 8) * 25 + n0]     = acc[nt][2];
            accs[(t0 + 8) * 25 + n0 + 1] = acc[nt][3];
        }
    }
    __syncthreads();

    if (tid < MTILE) {
        const float ap  = *a_pre_p;
        const float apo = *a_post_p;
        const float ar  = *a_res_p;
        const int gtok = tokbase + tid;

        float h[NOUT];
        #pragma unroll
        for (int o = 0; o < NOUT; o++) h[o] = accs[tid * 25 + o];

        float* out_pre  = out;
        float* out_post = out + (size_t)TOKENS * 4;
        float* out_res  = out + (size_t)TOKENS * 8;

        #pragma unroll
        for (int o = 0; o < 4; o++) {
            float z = ap * h[o] + b_pre[o];
            out_pre[(size_t)gtok * 4 + o] = 1.f / (1.f + __expf(-z));
        }
        #pragma unroll
        for (int o = 0; o < 4; o++) {
            float z = apo * h[4 + o] + b_post[o];
            out_post[(size_t)gtok * 4 + o] = 2.f / (1.f + __expf(-z));
        }

        // Sinkhorn-Knopp, linear domain (== log-domain reference exactly in exact arithmetic)
        float P[16];
        #pragma unroll
        for (int i = 0; i < 16; i++) P[i] = __expf(ar * h[8 + i] + b_res[i]);

        #pragma unroll 1
        for (int it = 0; it < 20; it++) {
            #pragma unroll
            for (int i = 0; i < 4; i++) {
                float srow = P[i*4] + P[i*4+1] + P[i*4+2] + P[i*4+3];
                float r = 1.f / srow;
                P[i*4] *= r; P[i*4+1] *= r; P[i*4+2] *= r; P[i*4+3] *= r;
            }
            #pragma unroll
            for (int j = 0; j < 4; j++) {
                float scol = P[j] + P[4+j] + P[8+j] + P[12+j];
                float r = 1.f / scol;
                P[j] *= r; P[4+j] *= r; P[8+j] *= r; P[12+j] *= r;
            }
        }
        #pragma unroll
        for (int i = 0; i < 16; i++) out_res[(size_t)gtok * 16 + i] = P[i];
    }
}

extern "C" void kernel_launch(void* const* d_in, const int* in_sizes, int n_in,
                              void* d_out, int out_size) {
    const float* x      = (const float*)d_in[0];
    const float* a_pre  = (const float*)d_in[1];
    const float* a_post = (const float*)d_in[2];
    const float* a_res  = (const float*)d_in[3];
    const float* b_pre  = (const float*)d_in[4];
    const float* b_post = (const float*)d_in[5];
    const float* b_res  = (const float*)d_in[6];
    const float* W_pre  = (const float*)d_in[7];
    const float* W_post = (const float*)d_in[8];
    const float* W_res  = (const float*)d_in[9];

    mhc_kernel<<<TOKENS / MTILE, NTHREADS>>>(
        x, a_pre, a_post, a_res, b_pre, b_post, b_res,
        W_pre, W_post, W_res, (float*)d_out);
}